// round 2
// baseline (speedup 1.0000x reference)
#include <cuda_runtime.h>
#include <cstdint>
#include <math.h>

// ============================================================================
// MoE (top-2 of 8 experts), D=1024, H=4096, O=1024, T=8192 tokens.
// tcgen05 is NOT available (harness PTX target is sm_103, not sm_103a), so the
// GEMMs use baseline mma.sync tf32 (m16n8k8) with cp.async pipelines.
// Pipeline: router -> setup -> gather -> grouped GEMM1 (relu) -> GEMM2 ->
//           combine (+ lb_loss tail).
// ============================================================================

#define T_TOK   8192
#define DMODEL  1024
#define DHID    4096
#define DOUTD   1024
#define NEXP    8
#define ROWS_CAP 17408   // 16384 + 8*128 padding

// GEMM tile config
#define BM 128
#define BN 256
#define BK 32            // floats per k-chunk = 128 B per row

#define SMEM_A_BYTES (BM * BK * 4)          // 16384
#define SMEM_B_BYTES (BN * BK * 4)          // 32768
#define SMEM_STAGE   (SMEM_A_BYTES + SMEM_B_BYTES)  // 49152
#define DSMEM_BYTES  (2 * SMEM_STAGE)       // 98304

// ---------------- device scratch (static: no allocation) ----------------
__device__ float g_perm[(size_t)ROWS_CAP * DMODEL];
__device__ float g_h   [(size_t)ROWS_CAP * DHID];
__device__ float g_y   [(size_t)ROWS_CAP * DOUTD];
__device__ float g_probs[T_TOK * NEXP];
__device__ float g_gate [T_TOK * 2];
__device__ int   g_topk [T_TOK * 2];
__device__ int   g_spos [T_TOK * 2];
__device__ int   g_counts[NEXP];
__device__ int   g_cursor[NEXP];
__device__ int   g_offsets[NEXP + 1];
__device__ float g_lb[1];

// ---------------- PTX helpers ----------------
__device__ __forceinline__ uint32_t smem_to_u32(const void* p) {
    uint32_t a;
    asm("{ .reg .u64 t; cvta.to.shared.u64 t, %1; cvt.u32.u64 %0, t; }" : "=r"(a) : "l"(p));
    return a;
}
__device__ __forceinline__ uint32_t f2tf32(float v) {
    uint32_t r;
    asm("cvt.rna.tf32.f32 %0, %1;" : "=r"(r) : "f"(v));
    return r;
}
__device__ __forceinline__ float lds_f(uint32_t a) {
    float v;
    asm volatile("ld.shared.f32 %0, [%1];" : "=f"(v) : "r"(a));
    return v;
}
#define CP_ASYNC16(dst, src) \
    asm volatile("cp.async.cg.shared.global [%0], [%1], 16;" :: "r"(dst), "l"(src) : "memory")
#define CP_COMMIT() asm volatile("cp.async.commit_group;" ::: "memory")
#define CP_WAIT1()  asm volatile("cp.async.wait_group 1;" ::: "memory")
#define CP_WAIT0()  asm volatile("cp.async.wait_group 0;" ::: "memory")

__device__ __forceinline__ void mma1688(float* c, const uint32_t* a, uint32_t b0, uint32_t b1) {
    asm volatile(
        "mma.sync.aligned.m16n8k8.row.col.f32.tf32.tf32.f32 "
        "{%0,%1,%2,%3}, {%4,%5,%6,%7}, {%8,%9}, {%0,%1,%2,%3};"
        : "+f"(c[0]), "+f"(c[1]), "+f"(c[2]), "+f"(c[3])
        : "r"(a[0]), "r"(a[1]), "r"(a[2]), "r"(a[3]), "r"(b0), "r"(b1));
}

// ============================================================================
// Phase kernels
// ============================================================================
__global__ void zero_counts_kernel() {
    if (threadIdx.x < NEXP) g_counts[threadIdx.x] = 0;
}

// router: 8 warps/block, one token per warp
__global__ void router_kernel(const float* __restrict__ x, const float* __restrict__ rw,
                              const float* __restrict__ rb) {
    int warp = threadIdx.x >> 5, lane = threadIdx.x & 31;
    int t = blockIdx.x * 8 + warp;
    const float* xp = x + (size_t)t * DMODEL;
    float xr[32];
#pragma unroll
    for (int i = 0; i < 32; i++) xr[i] = xp[i * 32 + lane];
    float lg[NEXP];
#pragma unroll
    for (int e = 0; e < NEXP; e++) {
        const float* wp = rw + e * DMODEL;
        float s = 0.f;
#pragma unroll
        for (int i = 0; i < 32; i++) s += xr[i] * wp[i * 32 + lane];
#pragma unroll
        for (int o = 16; o; o >>= 1) s += __shfl_xor_sync(0xFFFFFFFFu, s, o);
        lg[e] = s + rb[e];
    }
    if (lane == 0) {
        float mx = lg[0];
#pragma unroll
        for (int e = 1; e < NEXP; e++) mx = fmaxf(mx, lg[e]);
        float p[NEXP], sum = 0.f;
#pragma unroll
        for (int e = 0; e < NEXP; e++) { p[e] = expf(lg[e] - mx); sum += p[e]; }
        float inv = 1.f / sum;
#pragma unroll
        for (int e = 0; e < NEXP; e++) { p[e] *= inv; g_probs[t * NEXP + e] = p[e]; }
        int i0 = 0;
#pragma unroll
        for (int e = 1; e < NEXP; e++) if (p[e] > p[i0]) i0 = e;
        int i1 = (i0 == 0) ? 1 : 0;
#pragma unroll
        for (int e = 0; e < NEXP; e++) if (e != i0 && e != i1 && p[e] > p[i1]) i1 = e;
        float w0 = p[i0], w1 = p[i1], ws = 1.f / (w0 + w1);
        g_gate[t * 2 + 0] = w0 * ws;
        g_gate[t * 2 + 1] = w1 * ws;
        g_topk[t * 2 + 0] = i0;
        g_topk[t * 2 + 1] = i1;
        atomicAdd(&g_counts[i0], 1);
        atomicAdd(&g_counts[i1], 1);
    }
}

// setup: deterministic mean-prob reduction, lb_loss, padded offsets, cursors
__global__ void setup_kernel() {
    __shared__ float sp[NEXP];
    int warp = threadIdx.x >> 5, lane = threadIdx.x & 31;
    if (warp < NEXP) {
        float s = 0.f;
        for (int t = lane; t < T_TOK; t += 32) s += g_probs[t * NEXP + warp];
#pragma unroll
        for (int o = 16; o; o >>= 1) s += __shfl_xor_sync(0xFFFFFFFFu, s, o);
        if (lane == 0) sp[warp] = s;
    }
    __syncthreads();
    if (threadIdx.x == 0) {
        int off = 0;
        float l = 0.f;
        for (int e = 0; e < NEXP; e++) {
            g_offsets[e] = off;
            off += ((g_counts[e] + BM - 1) / BM) * BM;
            g_cursor[e] = 0;
            l += ((float)g_counts[e] / (float)(T_TOK * 2)) * (sp[e] / (float)T_TOK);
        }
        g_offsets[NEXP] = off;
        g_lb[0] = 0.01f * (float)NEXP * l;
    }
}

// gather: one warp per (token, slot); copies x row into grouped layout
__global__ void scatter_kernel(const float* __restrict__ x) {
    int wslot = blockIdx.x * 8 + (threadIdx.x >> 5);   // 0..16383
    int lane = threadIdx.x & 31;
    int t = wslot >> 1, k = wslot & 1;
    int e = g_topk[t * 2 + k];
    int pos = 0;
    if (lane == 0) {
        pos = g_offsets[e] + atomicAdd(&g_cursor[e], 1);
        g_spos[t * 2 + k] = pos;
    }
    pos = __shfl_sync(0xFFFFFFFFu, pos, 0);
    const float4* src = (const float4*)(x + (size_t)t * DMODEL);
    float4* dst = (float4*)(g_perm + (size_t)pos * DMODEL);
#pragma unroll
    for (int j = 0; j < 8; j++) dst[lane + j * 32] = src[lane + j * 32];
}

// ============================================================================
// Grouped GEMM via mma.sync tf32: C[m,n] = act(A[m,:].Bw[e][n,:] + bias[e][n])
// Block tile 128x256, BK=32, 8 warps (2Mx4N), warp tile 64x64, double-buffered
// cp.async. SMEM rows are 32 floats (128B); float4 columns XOR-swizzled by
// (r&7) -> conflict-free stores and fragment loads.
// MODE 0: A=g_perm, C=g_h (relu).  MODE 1: A=g_h, C=g_y.
// ============================================================================
template <int KTOT, int NTOT, bool RELU, int MODE>
__global__ __launch_bounds__(256, 1) void gemm_kernel(const float* __restrict__ Bw,
                                                      const float* __restrict__ bias) {
    const float* A = (MODE == 0) ? g_perm : g_h;
    float* C = (MODE == 0) ? g_h : g_y;

    int e = blockIdx.z;
    int end = g_offsets[e + 1];
    int row0 = g_offsets[e] + (int)blockIdx.y * BM;
    if (row0 >= end) return;
    int n0 = blockIdx.x * BN;

    extern __shared__ char smem[];
    uint32_t sb = smem_to_u32(smem);
    int tid = threadIdx.x;
    int wid = tid >> 5, lane = tid & 31;
    int g = lane >> 2, t = lane & 3;
    int wm = wid >> 2;          // 0..1 -> m offset wm*64
    int wn = wid & 3;           // 0..3 -> n offset wn*64

    const float* Ag = A + (size_t)row0 * KTOT;
    const float* Bg = Bw + (size_t)e * NTOT * KTOT + (size_t)n0 * KTOT;

    // ---- async loader for one BK chunk into buffer `buf` ----
    auto load_chunk = [&](int it, int buf) {
        int k0 = it * BK;
        uint32_t sA = sb + buf * SMEM_STAGE;
        uint32_t sB = sA + SMEM_A_BYTES;
#pragma unroll
        for (int i = 0; i < 4; i++) {           // A: 128 rows x 8 float4
            int idx = tid + i * 256;
            int r = idx >> 3, c4 = idx & 7;
            uint32_t dst = sA + (uint32_t)(r * 8 + (c4 ^ (r & 7))) * 16;
            CP_ASYNC16(dst, Ag + (size_t)r * KTOT + k0 + c4 * 4);
        }
#pragma unroll
        for (int i = 0; i < 8; i++) {           // B: 256 rows x 8 float4
            int idx = tid + i * 256;
            int r = idx >> 3, c4 = idx & 7;
            uint32_t dst = sB + (uint32_t)(r * 8 + (c4 ^ (r & 7))) * 16;
            CP_ASYNC16(dst, Bg + (size_t)r * KTOT + k0 + c4 * 4);
        }
        CP_COMMIT();
    };

    float acc[4][8][4];
#pragma unroll
    for (int mt = 0; mt < 4; mt++)
#pragma unroll
        for (int nt = 0; nt < 8; nt++)
#pragma unroll
            for (int j = 0; j < 4; j++) acc[mt][nt][j] = 0.f;

    constexpr int NIT = KTOT / BK;
    load_chunk(0, 0);

    for (int it = 0; it < NIT; ++it) {
        int buf = it & 1;
        if (it + 1 < NIT) { load_chunk(it + 1, buf ^ 1); CP_WAIT1(); }
        else              { CP_WAIT0(); }
        __syncthreads();

        uint32_t sA = sb + buf * SMEM_STAGE;
        uint32_t sB = sA + SMEM_A_BYTES;
        // rows of interest all have (r & 7) == g, so the swizzled column
        // offset is row-independent:
#pragma unroll
        for (int kk = 0; kk < 4; kk++) {
            uint32_t col0 = (uint32_t)(((2 * kk) ^ g) * 16 + t * 4);
            uint32_t col1 = (uint32_t)(((2 * kk + 1) ^ g) * 16 + t * 4);
            uint32_t af[4][4];
#pragma unroll
            for (int mt = 0; mt < 4; mt++) {
                uint32_t r0 = (uint32_t)(wm * 64 + mt * 16 + g) * 128;
                af[mt][0] = f2tf32(lds_f(sA + r0 + col0));
                af[mt][1] = f2tf32(lds_f(sA + r0 + 8 * 128 + col0));
                af[mt][2] = f2tf32(lds_f(sA + r0 + col1));
                af[mt][3] = f2tf32(lds_f(sA + r0 + 8 * 128 + col1));
            }
#pragma unroll
            for (int nt = 0; nt < 8; nt++) {
                uint32_t rn = (uint32_t)(wn * 64 + nt * 8 + g) * 128;
                uint32_t b0 = f2tf32(lds_f(sB + rn + col0));
                uint32_t b1 = f2tf32(lds_f(sB + rn + col1));
#pragma unroll
                for (int mt = 0; mt < 4; mt++) mma1688(acc[mt][nt], af[mt], b0, b1);
            }
        }
        __syncthreads();
    }

    // ---- epilogue: bias (+relu), direct float2 stores ----
    const float* bp = bias + (size_t)e * NTOT + n0 + wn * 64;
#pragma unroll
    for (int nt = 0; nt < 8; nt++) {
        int col = nt * 8 + 2 * t;
        float2 bv = *(const float2*)(bp + col);
#pragma unroll
        for (int mt = 0; mt < 4; mt++) {
            int r0 = row0 + wm * 64 + mt * 16 + g;
            float2 v0, v1;
            v0.x = acc[mt][nt][0] + bv.x; v0.y = acc[mt][nt][1] + bv.y;
            v1.x = acc[mt][nt][2] + bv.x; v1.y = acc[mt][nt][3] + bv.y;
            if (RELU) {
                v0.x = fmaxf(v0.x, 0.f); v0.y = fmaxf(v0.y, 0.f);
                v1.x = fmaxf(v1.x, 0.f); v1.y = fmaxf(v1.y, 0.f);
            }
            float* cp0 = C + (size_t)r0 * NTOT + n0 + wn * 64 + col;
            *(float2*)cp0 = v0;
            *(float2*)(cp0 + (size_t)8 * NTOT) = v1;
        }
    }
}

// combine: out[t] = w0*Y[p0] + w1*Y[p1]  (deterministic, no atomics)
__global__ void combine_kernel(float* __restrict__ out) {
    int t = blockIdx.x;
    int d4 = threadIdx.x;   // 256 float4 per row
    float w0 = g_gate[t * 2 + 0], w1 = g_gate[t * 2 + 1];
    int p0 = g_spos[t * 2 + 0], p1 = g_spos[t * 2 + 1];
    float4 y0 = ((const float4*)(g_y + (size_t)p0 * DOUTD))[d4];
    float4 y1 = ((const float4*)(g_y + (size_t)p1 * DOUTD))[d4];
    float4 o;
    o.x = w0 * y0.x + w1 * y1.x;
    o.y = w0 * y0.y + w1 * y1.y;
    o.z = w0 * y0.z + w1 * y1.z;
    o.w = w0 * y0.w + w1 * y1.w;
    ((float4*)(out + (size_t)t * DOUTD))[d4] = o;
}

__global__ void lb_write_kernel(float* dst, int n) {
    int i = threadIdx.x;
    if (i < n) dst[i] = g_lb[0];
}

// ============================================================================
extern "C" void kernel_launch(void* const* d_in, const int* in_sizes, int n_in,
                              void* d_out, int out_size) {
    const float* x  = (const float*)d_in[0];
    const float* rw = (const float*)d_in[1];
    const float* rb = (const float*)d_in[2];
    const float* w1 = (const float*)d_in[3];
    const float* b1 = (const float*)d_in[4];
    const float* w2 = (const float*)d_in[5];
    const float* b2 = (const float*)d_in[6];
    float* out = (float*)d_out;

    cudaFuncSetAttribute(gemm_kernel<DMODEL, DHID, true, 0>,
                         cudaFuncAttributeMaxDynamicSharedMemorySize, DSMEM_BYTES);
    cudaFuncSetAttribute(gemm_kernel<DHID, DOUTD, false, 1>,
                         cudaFuncAttributeMaxDynamicSharedMemorySize, DSMEM_BYTES);

    zero_counts_kernel<<<1, 32>>>();
    router_kernel<<<T_TOK / 8, 256>>>(x, rw, rb);
    setup_kernel<<<1, 256>>>();
    scatter_kernel<<<(T_TOK * 2) / 8, 256>>>(x);
    // GEMM1: [rows,1024] x w1[e][4096,1024]^T -> g_h (relu). N tiles 4096/256=16
    gemm_kernel<DMODEL, DHID, true, 0><<<dim3(DHID / BN, 64, NEXP), 256, DSMEM_BYTES>>>(w1, b1);
    // GEMM2: [rows,4096] x w2[e][1024,4096]^T -> g_y. N tiles 1024/256=4
    gemm_kernel<DHID, DOUTD, false, 1><<<dim3(DOUTD / BN, 64, NEXP), 256, DSMEM_BYTES>>>(w2, b2);
    combine_kernel<<<T_TOK, 256>>>(out);

    long long tail = (long long)out_size - (long long)T_TOK * DOUTD;
    if (tail > 0) {
        int n = (tail > 32) ? 32 : (int)tail;
        lb_write_kernel<<<1, 32>>>(out + (size_t)T_TOK * DOUTD, n);
    }
}

// round 6
// speedup vs baseline: 1.0502x; 1.0502x over previous
#include <cuda_runtime.h>
#include <cstdint>
#include <math.h>

// ============================================================================
// MoE (top-2 of 8 experts), D=1024, H=4096, O=1024, T=8192 tokens.
// tcgen05 unavailable (harness targets plain sm_103): GEMMs use mma.sync tf32
// m16n8k8. All operands are pre-rounded to tf32 in GLOBAL memory (prepass for
// weights, scatter/epilogue for activations) so the GEMM inner loop is pure
// LDS + HMMA. 3-stage cp.async pipeline, 1 sync/chunk, packed tile grid.
// ============================================================================

#define T_TOK   8192
#define DMODEL  1024
#define DHID    4096
#define DOUTD   1024
#define NEXP    8
#define ROWS_CAP 17408   // 16384 + 8*128 padding
#define MAX_MTILES 136   // ceil(ROWS_CAP/128)

// GEMM tile config
#define BM 128
#define BN 256
#define BK 32            // floats per k-chunk = 128 B per row

#define SMEM_A_BYTES (BM * BK * 4)          // 16384
#define SMEM_B_BYTES (BN * BK * 4)          // 32768
#define SMEM_STAGE   (SMEM_A_BYTES + SMEM_B_BYTES)  // 49152
#define NSTAGE 3
#define DSMEM_BYTES  (NSTAGE * SMEM_STAGE)  // 147456

// ---------------- device scratch (static: no allocation) ----------------
__device__ float g_perm[(size_t)ROWS_CAP * DMODEL];
__device__ float g_h   [(size_t)ROWS_CAP * DHID];
__device__ float g_y   [(size_t)ROWS_CAP * DOUTD];
__device__ float g_w1r [(size_t)NEXP * DHID * DMODEL];   // tf32-rounded w1
__device__ float g_w2r [(size_t)NEXP * DOUTD * DHID];    // tf32-rounded w2
__device__ float g_probs[T_TOK * NEXP];
__device__ float g_gate [T_TOK * 2];
__device__ int   g_topk [T_TOK * 2];
__device__ int   g_spos [T_TOK * 2];
__device__ int   g_counts[NEXP];
__device__ int   g_cursor[NEXP];
__device__ int   g_offsets[NEXP + 1];
__device__ float g_lb[1];

// ---------------- PTX helpers ----------------
__device__ __forceinline__ uint32_t smem_to_u32(const void* p) {
    uint32_t a;
    asm("{ .reg .u64 t; cvta.to.shared.u64 t, %1; cvt.u32.u64 %0, t; }" : "=r"(a) : "l"(p));
    return a;
}
__device__ __forceinline__ uint32_t f2tf32(float v) {
    uint32_t r;
    asm("cvt.rna.tf32.f32 %0, %1;" : "=r"(r) : "f"(v));
    return r;
}
__device__ __forceinline__ uint32_t lds_u(uint32_t a) {
    uint32_t v;
    asm volatile("ld.shared.b32 %0, [%1];" : "=r"(v) : "r"(a));
    return v;
}
#define CP_ASYNC16(dst, src) \
    asm volatile("cp.async.cg.shared.global [%0], [%1], 16;" :: "r"(dst), "l"(src) : "memory")
#define CP_COMMIT() asm volatile("cp.async.commit_group;" ::: "memory")
#define CP_WAIT1()  asm volatile("cp.async.wait_group 1;" ::: "memory")
#define CP_WAIT0()  asm volatile("cp.async.wait_group 0;" ::: "memory")

__device__ __forceinline__ void mma1688(float* c, const uint32_t* a, uint32_t b0, uint32_t b1) {
    asm volatile(
        "mma.sync.aligned.m16n8k8.row.col.f32.tf32.tf32.f32 "
        "{%0,%1,%2,%3}, {%4,%5,%6,%7}, {%8,%9}, {%0,%1,%2,%3};"
        : "+f"(c[0]), "+f"(c[1]), "+f"(c[2]), "+f"(c[3])
        : "r"(a[0]), "r"(a[1]), "r"(a[2]), "r"(a[3]), "r"(b0), "r"(b1));
}

// ============================================================================
// Phase kernels
// ============================================================================
__global__ void zero_counts_kernel() {
    if (threadIdx.x < NEXP) g_counts[threadIdx.x] = 0;
}

// tf32-round copy (weights prepass)
__global__ void round_kernel(const float* __restrict__ src, float* __restrict__ dst,
                             int n4) {
    int i = blockIdx.x * blockDim.x + threadIdx.x;
    int stride = gridDim.x * blockDim.x;
    for (; i < n4; i += stride) {
        float4 v = ((const float4*)src)[i];
        uint4 r = make_uint4(f2tf32(v.x), f2tf32(v.y), f2tf32(v.z), f2tf32(v.w));
        ((uint4*)dst)[i] = r;
    }
}

// router: 8 warps/block, one token per warp
__global__ void router_kernel(const float* __restrict__ x, const float* __restrict__ rw,
                              const float* __restrict__ rb) {
    int warp = threadIdx.x >> 5, lane = threadIdx.x & 31;
    int t = blockIdx.x * 8 + warp;
    const float* xp = x + (size_t)t * DMODEL;
    float xr[32];
#pragma unroll
    for (int i = 0; i < 32; i++) xr[i] = xp[i * 32 + lane];
    float lg[NEXP];
#pragma unroll
    for (int e = 0; e < NEXP; e++) {
        const float* wp = rw + e * DMODEL;
        float s = 0.f;
#pragma unroll
        for (int i = 0; i < 32; i++) s += xr[i] * wp[i * 32 + lane];
#pragma unroll
        for (int o = 16; o; o >>= 1) s += __shfl_xor_sync(0xFFFFFFFFu, s, o);
        lg[e] = s + rb[e];
    }
    if (lane == 0) {
        float mx = lg[0];
#pragma unroll
        for (int e = 1; e < NEXP; e++) mx = fmaxf(mx, lg[e]);
        float p[NEXP], sum = 0.f;
#pragma unroll
        for (int e = 0; e < NEXP; e++) { p[e] = expf(lg[e] - mx); sum += p[e]; }
        float inv = 1.f / sum;
#pragma unroll
        for (int e = 0; e < NEXP; e++) { p[e] *= inv; g_probs[t * NEXP + e] = p[e]; }
        int i0 = 0;
#pragma unroll
        for (int e = 1; e < NEXP; e++) if (p[e] > p[i0]) i0 = e;
        int i1 = (i0 == 0) ? 1 : 0;
#pragma unroll
        for (int e = 0; e < NEXP; e++) if (e != i0 && e != i1 && p[e] > p[i1]) i1 = e;
        float w0 = p[i0], w1 = p[i1], ws = 1.f / (w0 + w1);
        g_gate[t * 2 + 0] = w0 * ws;
        g_gate[t * 2 + 1] = w1 * ws;
        g_topk[t * 2 + 0] = i0;
        g_topk[t * 2 + 1] = i1;
        atomicAdd(&g_counts[i0], 1);
        atomicAdd(&g_counts[i1], 1);
    }
}

// setup: deterministic mean-prob reduction, lb_loss, padded offsets, cursors
__global__ void setup_kernel() {
    __shared__ float sp[NEXP];
    int warp = threadIdx.x >> 5, lane = threadIdx.x & 31;
    if (warp < NEXP) {
        float s = 0.f;
        for (int t = lane; t < T_TOK; t += 32) s += g_probs[t * NEXP + warp];
#pragma unroll
        for (int o = 16; o; o >>= 1) s += __shfl_xor_sync(0xFFFFFFFFu, s, o);
        if (lane == 0) sp[warp] = s;
    }
    __syncthreads();
    if (threadIdx.x == 0) {
        int off = 0;
        float l = 0.f;
        for (int e = 0; e < NEXP; e++) {
            g_offsets[e] = off;
            off += ((g_counts[e] + BM - 1) / BM) * BM;
            g_cursor[e] = 0;
            l += ((float)g_counts[e] / (float)(T_TOK * 2)) * (sp[e] / (float)T_TOK);
        }
        g_offsets[NEXP] = off;
        g_lb[0] = 0.01f * (float)NEXP * l;
    }
}

// gather: one warp per (token, slot); tf32-rounds x into grouped layout
__global__ void scatter_kernel(const float* __restrict__ x) {
    int wslot = blockIdx.x * 8 + (threadIdx.x >> 5);   // 0..16383
    int lane = threadIdx.x & 31;
    int t = wslot >> 1, k = wslot & 1;
    int e = g_topk[t * 2 + k];
    int pos = 0;
    if (lane == 0) {
        pos = g_offsets[e] + atomicAdd(&g_cursor[e], 1);
        g_spos[t * 2 + k] = pos;
    }
    pos = __shfl_sync(0xFFFFFFFFu, pos, 0);
    const float4* src = (const float4*)(x + (size_t)t * DMODEL);
    uint4* dst = (uint4*)(g_perm + (size_t)pos * DMODEL);
#pragma unroll
    for (int j = 0; j < 8; j++) {
        float4 v = src[lane + j * 32];
        dst[lane + j * 32] = make_uint4(f2tf32(v.x), f2tf32(v.y), f2tf32(v.z), f2tf32(v.w));
    }
}

// ============================================================================
// Grouped GEMM via mma.sync tf32. Operands already tf32-rounded in global.
// Block tile 128x256, BK=32, 8 warps (2Mx4N), warp tile 64x64, 3-stage
// cp.async pipeline, one __syncthreads per chunk. Packed y-grid: row tile
// blockIdx.y*128 mapped to its expert via g_offsets scan.
// MODE 0: A=g_perm, C=g_h (relu, tf32-rounded store).  MODE 1: A=g_h, C=g_y.
// ============================================================================
template <int KTOT, int NTOT, bool RELU, int MODE>
__global__ __launch_bounds__(256, 1) void gemm_kernel(const float* __restrict__ Bw,
                                                      const float* __restrict__ bias) {
    const float* A = (MODE == 0) ? g_perm : g_h;
    float* C = (MODE == 0) ? g_h : g_y;

    int row0 = (int)blockIdx.y * BM;
    if (row0 >= g_offsets[NEXP]) return;
    int e = 0;
#pragma unroll
    for (int i = 1; i < NEXP; i++) if (row0 >= g_offsets[i]) e = i;
    int n0 = blockIdx.x * BN;

    extern __shared__ char smem[];
    uint32_t sb = smem_to_u32(smem);
    int tid = threadIdx.x;
    int wid = tid >> 5, lane = tid & 31;
    int g = lane >> 2, t = lane & 3;
    int wm = wid >> 2;          // 0..1 -> m offset wm*64
    int wn = wid & 3;           // 0..3 -> n offset wn*64

    const float* Ag = A + (size_t)row0 * KTOT;
    const float* Bg = Bw + (size_t)e * NTOT * KTOT + (size_t)n0 * KTOT;

    auto load_chunk = [&](int it, int buf) {
        int k0 = it * BK;
        uint32_t sA = sb + buf * SMEM_STAGE;
        uint32_t sB = sA + SMEM_A_BYTES;
#pragma unroll
        for (int i = 0; i < 4; i++) {           // A: 128 rows x 8 float4
            int idx = tid + i * 256;
            int r = idx >> 3, c4 = idx & 7;
            uint32_t dst = sA + (uint32_t)(r * 8 + (c4 ^ (r & 7))) * 16;
            CP_ASYNC16(dst, Ag + (size_t)r * KTOT + k0 + c4 * 4);
        }
#pragma unroll
        for (int i = 0; i < 8; i++) {           // B: 256 rows x 8 float4
            int idx = tid + i * 256;
            int r = idx >> 3, c4 = idx & 7;
            uint32_t dst = sB + (uint32_t)(r * 8 + (c4 ^ (r & 7))) * 16;
            CP_ASYNC16(dst, Bg + (size_t)r * KTOT + k0 + c4 * 4);
        }
        CP_COMMIT();
    };

    float acc[4][8][4];
#pragma unroll
    for (int mt = 0; mt < 4; mt++)
#pragma unroll
        for (int nt = 0; nt < 8; nt++)
#pragma unroll
            for (int j = 0; j < 4; j++) acc[mt][nt][j] = 0.f;

    constexpr int NIT = KTOT / BK;
    load_chunk(0, 0);
    load_chunk(1, 1);

    int buf = 0;
    for (int it = 0; it < NIT; ++it) {
        if (it == NIT - 1) { CP_WAIT0(); } else { CP_WAIT1(); }
        __syncthreads();
        if (it + 2 < NIT) {
            int nb = buf + 2; if (nb >= NSTAGE) nb -= NSTAGE;
            load_chunk(it + 2, nb);
        }

        uint32_t sA = sb + buf * SMEM_STAGE;
        uint32_t sB = sA + SMEM_A_BYTES;
        // all fragment rows satisfy (r & 7) == g -> swizzled column offset is
        // row-independent:
#pragma unroll
        for (int kk = 0; kk < 4; kk++) {
            uint32_t col0 = (uint32_t)(((2 * kk) ^ g) * 16 + t * 4);
            uint32_t col1 = (uint32_t)(((2 * kk + 1) ^ g) * 16 + t * 4);
            uint32_t af[4][4];
#pragma unroll
            for (int mt = 0; mt < 4; mt++) {
                uint32_t r0 = (uint32_t)(wm * 64 + mt * 16 + g) * 128;
                af[mt][0] = lds_u(sA + r0 + col0);
                af[mt][1] = lds_u(sA + r0 + 8 * 128 + col0);
                af[mt][2] = lds_u(sA + r0 + col1);
                af[mt][3] = lds_u(sA + r0 + 8 * 128 + col1);
            }
#pragma unroll
            for (int nt = 0; nt < 8; nt++) {
                uint32_t rn = (uint32_t)(wn * 64 + nt * 8 + g) * 128;
                uint32_t b0 = lds_u(sB + rn + col0);
                uint32_t b1 = lds_u(sB + rn + col1);
#pragma unroll
                for (int mt = 0; mt < 4; mt++) mma1688(acc[mt][nt], af[mt], b0, b1);
            }
        }
        buf = (buf == NSTAGE - 1) ? 0 : buf + 1;
    }

    // ---- epilogue: bias (+relu), MODE0 tf32-rounds for GEMM2 input ----
    const float* bp = bias + (size_t)e * NTOT + n0 + wn * 64;
#pragma unroll
    for (int nt = 0; nt < 8; nt++) {
        int col = nt * 8 + 2 * t;
        float2 bv = *(const float2*)(bp + col);
#pragma unroll
        for (int mt = 0; mt < 4; mt++) {
            int r0 = row0 + wm * 64 + mt * 16 + g;
            float v[4];
            v[0] = acc[mt][nt][0] + bv.x; v[1] = acc[mt][nt][1] + bv.y;
            v[2] = acc[mt][nt][2] + bv.x; v[3] = acc[mt][nt][3] + bv.y;
            if (RELU) {
#pragma unroll
                for (int j = 0; j < 4; j++) v[j] = fmaxf(v[j], 0.f);
            }
            if (MODE == 0) {
#pragma unroll
                for (int j = 0; j < 4; j++) v[j] = __uint_as_float(f2tf32(v[j]));
            }
            float* cp0 = C + (size_t)r0 * NTOT + n0 + wn * 64 + col;
            *(float2*)cp0 = make_float2(v[0], v[1]);
            *(float2*)(cp0 + (size_t)8 * NTOT) = make_float2(v[2], v[3]);
        }
    }
}

// combine: out[t] = w0*Y[p0] + w1*Y[p1]  (deterministic, no atomics)
__global__ void combine_kernel(float* __restrict__ out) {
    int t = blockIdx.x;
    int d4 = threadIdx.x;   // 256 float4 per row
    float w0 = g_gate[t * 2 + 0], w1 = g_gate[t * 2 + 1];
    int p0 = g_spos[t * 2 + 0], p1 = g_spos[t * 2 + 1];
    float4 y0 = ((const float4*)(g_y + (size_t)p0 * DOUTD))[d4];
    float4 y1 = ((const float4*)(g_y + (size_t)p1 * DOUTD))[d4];
    float4 o;
    o.x = w0 * y0.x + w1 * y1.x;
    o.y = w0 * y0.y + w1 * y1.y;
    o.z = w0 * y0.z + w1 * y1.z;
    o.w = w0 * y0.w + w1 * y1.w;
    ((float4*)(out + (size_t)t * DOUTD))[d4] = o;
}

__global__ void lb_write_kernel(float* dst, int n) {
    int i = threadIdx.x;
    if (i < n) dst[i] = g_lb[0];
}

// ============================================================================
extern "C" void kernel_launch(void* const* d_in, const int* in_sizes, int n_in,
                              void* d_out, int out_size) {
    const float* x  = (const float*)d_in[0];
    const float* rw = (const float*)d_in[1];
    const float* rb = (const float*)d_in[2];
    const float* w1 = (const float*)d_in[3];
    const float* b1 = (const float*)d_in[4];
    const float* w2 = (const float*)d_in[5];
    const float* b2 = (const float*)d_in[6];
    float* out = (float*)d_out;

    cudaFuncSetAttribute(gemm_kernel<DMODEL, DHID, true, 0>,
                         cudaFuncAttributeMaxDynamicSharedMemorySize, DSMEM_BYTES);
    cudaFuncSetAttribute(gemm_kernel<DHID, DOUTD, false, 1>,
                         cudaFuncAttributeMaxDynamicSharedMemorySize, DSMEM_BYTES);

    float* w1r; cudaGetSymbolAddress((void**)&w1r, g_w1r);
    float* w2r; cudaGetSymbolAddress((void**)&w2r, g_w2r);

    // weight tf32 prepass (amortized over ~17x/68x reuse in the GEMMs)
    round_kernel<<<1024, 256>>>(w1, w1r, NEXP * DHID * DMODEL / 4);
    round_kernel<<<1024, 256>>>(w2, w2r, NEXP * DOUTD * DHID / 4);

    zero_counts_kernel<<<1, 32>>>();
    router_kernel<<<T_TOK / 8, 256>>>(x, rw, rb);
    setup_kernel<<<1, 256>>>();
    scatter_kernel<<<(T_TOK * 2) / 8, 256>>>(x);
    // GEMM1: [rows,1024] x w1[e][4096,1024]^T -> g_h (relu)
    gemm_kernel<DMODEL, DHID, true, 0>
        <<<dim3(DHID / BN, MAX_MTILES, 1), 256, DSMEM_BYTES>>>(w1r, b1);
    // GEMM2: [rows,4096] x w2[e][1024,4096]^T -> g_y
    gemm_kernel<DHID, DOUTD, false, 1>
        <<<dim3(DOUTD / BN, MAX_MTILES, 1), 256, DSMEM_BYTES>>>(w2r, b2);
    combine_kernel<<<T_TOK, 256>>>(out);

    long long tail = (long long)out_size - (long long)T_TOK * DOUTD;
    if (tail > 0) {
        int n = (tail > 32) ? 32 : (int)tail;
        lb_write_kernel<<<1, 32>>>(out + (size_t)T_TOK * DOUTD, n);
    }
}